// round 1
// baseline (speedup 1.0000x reference)
#include <cuda_runtime.h>
#include <float.h>

// Problem constants (fixed by setup_inputs)
#define B_   2
#define D_   64
#define KDIM 67          // D + 3 (points ++ xyz)
#define N1_  16384
#define N2_  16384

// Tiling
#define BM 128
#define BN 128
#define TM 8
#define TN 8
#define NTH 256

// Scratch: |f2_j|^2 per (b, j). Static device global (no allocation).
__device__ float g_sq2[B_ * N2_];

// ---------------------------------------------------------------------------
// Kernel A: precompute |f2_j|^2 = sum_d points2^2 + sum_d xyz2^2
// ---------------------------------------------------------------------------
__global__ void sq2_kernel(const float* __restrict__ xyz2,
                           const float* __restrict__ points2) {
    int idx = blockIdx.x * blockDim.x + threadIdx.x;
    if (idx >= B_ * N2_) return;
    int b = idx / N2_;
    int j = idx % N2_;
    const float* p = points2 + (size_t)b * D_ * N2_ + j;
    float s = 0.f;
    #pragma unroll
    for (int d = 0; d < D_; d++) { float v = p[(size_t)d * N2_]; s += v * v; }
    const float* x = xyz2 + (size_t)b * 3 * N2_ + j;
    #pragma unroll
    for (int d = 0; d < 3; d++) { float v = x[(size_t)d * N2_]; s += v * v; }
    g_sq2[idx] = s;
}

// ---------------------------------------------------------------------------
// Kernel B: fused GEMM + streaming argmin + output epilogue.
// Block = (batch b, 128-query m-tile). A tile loaded once to SMEM; B tiles
// of 128 reference points streamed; 8x8 register tile of dot products per
// thread; score = |f2|^2 - 2*dot; running per-row argmin; cross-thread
// reduction + gather epilogue at the end.
// ---------------------------------------------------------------------------
__global__ void nn_kernel(const float* __restrict__ xyz1,
                          const float* __restrict__ xyz2,
                          const float* __restrict__ points1,
                          const float* __restrict__ points2,
                          float* __restrict__ out) {
    extern __shared__ float smem[];
    float* shA = smem;                   // [KDIM][BM]
    float* shB = smem + KDIM * BM;       // [KDIM][BN]
    float* shS = smem + 2 * KDIM * BM;   // [BN] : |f2|^2 for current tile

    const int b   = blockIdx.y;
    const int m0  = blockIdx.x * BM;
    const int tid = threadIdx.x;
    const int tx  = tid & 15;            // 0..15 -> n sub-tile
    const int ty  = tid >> 4;            // 0..15 -> m sub-tile

    const float* p1 = points1 + (size_t)b * D_ * N1_;
    const float* x1 = xyz1    + (size_t)b * 3  * N1_;
    const float* p2 = points2 + (size_t)b * D_ * N2_;
    const float* x2 = xyz2    + (size_t)b * 3  * N2_;

    // Load A tile [KDIM][BM] once (coalesced: contiguous 128-float rows)
    for (int idx = tid; idx < KDIM * BM; idx += NTH) {
        int k = idx >> 7;                // idx / 128
        int n = idx & 127;
        const float* src = (k < D_) ? (p1 + (size_t)k * N1_)
                                    : (x1 + (size_t)(k - D_) * N1_);
        shA[k * BM + n] = src[m0 + n];
    }

    float bestVal[TM];
    int   bestIdx[TM];
    #pragma unroll
    for (int i = 0; i < TM; i++) { bestVal[i] = FLT_MAX; bestIdx[i] = 0; }

    for (int n0 = 0; n0 < N2_; n0 += BN) {
        __syncthreads();   // protect shB/shS from previous iteration's readers
        for (int idx = tid; idx < KDIM * BN; idx += NTH) {
            int k = idx >> 7;
            int n = idx & 127;
            const float* src = (k < D_) ? (p2 + (size_t)k * N2_)
                                        : (x2 + (size_t)(k - D_) * N2_);
            shB[k * BN + n] = src[n0 + n];
        }
        if (tid < BN) shS[tid] = g_sq2[b * N2_ + n0 + tid];
        __syncthreads();

        float acc[TM][TN];
        #pragma unroll
        for (int i = 0; i < TM; i++)
            #pragma unroll
            for (int j = 0; j < TN; j++) acc[i][j] = 0.f;

        #pragma unroll 4
        for (int k = 0; k < KDIM; k++) {
            float4 a0 = *(const float4*)&shA[k * BM + ty * TM];
            float4 a1 = *(const float4*)&shA[k * BM + ty * TM + 4];
            float4 b0 = *(const float4*)&shB[k * BN + tx * TN];
            float4 b1 = *(const float4*)&shB[k * BN + tx * TN + 4];
            float av[TM] = {a0.x, a0.y, a0.z, a0.w, a1.x, a1.y, a1.z, a1.w};
            float bv[TN] = {b0.x, b0.y, b0.z, b0.w, b1.x, b1.y, b1.z, b1.w};
            #pragma unroll
            for (int i = 0; i < TM; i++)
                #pragma unroll
                for (int j = 0; j < TN; j++)
                    acc[i][j] += av[i] * bv[j];
        }

        // score = |f2_j|^2 - 2*dot ; running argmin per owned row
        #pragma unroll
        for (int j = 0; j < TN; j++) {
            int   jj = tx * TN + j;
            float s2 = shS[jj];
            int   gj = n0 + jj;
            #pragma unroll
            for (int i = 0; i < TM; i++) {
                float sc = s2 - 2.f * acc[i][j];
                if (sc < bestVal[i] || (sc == bestVal[i] && gj < bestIdx[i])) {
                    bestVal[i] = sc;
                    bestIdx[i] = gj;
                }
            }
        }
    }

    // Cross-thread argmin reduction: 16 candidates per row
    __syncthreads();
    float* sv = smem;                     // [BM][16] values
    int*   si = (int*)(smem + BM * 16);   // [BM][16] indices
    #pragma unroll
    for (int i = 0; i < TM; i++) {
        int row = ty * TM + i;
        sv[row * 16 + tx] = bestVal[i];
        si[row * 16 + tx] = bestIdx[i];
    }
    __syncthreads();

    if (tid < BM) {
        float bv = FLT_MAX;
        int   bi = 0x7FFFFFFF;
        #pragma unroll
        for (int t = 0; t < 16; t++) {
            float v  = sv[tid * 16 + t];
            int   ix = si[tid * 16 + t];
            if (v < bv || (v == bv && ix < bi)) { bv = v; bi = ix; }
        }
        int gi = m0 + tid;
        // Output layout (flattened, fp32): corres1 | corres2 | direction_xyz
        out[b * N1_ + gi]        = (float)gi;
        out[(B_ + b) * N1_ + gi] = (float)bi;
        float* dir = out + 2 * B_ * N1_;
        #pragma unroll
        for (int d = 0; d < 3; d++)
            dir[((size_t)b * 3 + d) * N1_ + gi] =
                x2[(size_t)d * N2_ + bi] - x1[(size_t)d * N1_ + gi];
    }
}

// ---------------------------------------------------------------------------
extern "C" void kernel_launch(void* const* d_in, const int* in_sizes, int n_in,
                              void* d_out, int out_size) {
    const float* xyz1    = (const float*)d_in[0];
    const float* xyz2    = (const float*)d_in[1];
    const float* points1 = (const float*)d_in[2];
    const float* points2 = (const float*)d_in[3];
    float* out = (float*)d_out;

    sq2_kernel<<<(B_ * N2_ + 255) / 256, 256>>>(xyz2, points2);

    int smem_bytes = (2 * KDIM * BM + BN) * sizeof(float);   // ~69 KB
    cudaFuncSetAttribute(nn_kernel,
                         cudaFuncAttributeMaxDynamicSharedMemorySize,
                         smem_bytes);
    dim3 grid(N1_ / BM, B_);
    nn_kernel<<<grid, NTH, smem_bytes>>>(xyz1, xyz2, points1, points2, out);
}

// round 2
// speedup vs baseline: 1.2193x; 1.2193x over previous
#include <cuda_runtime.h>
#include <float.h>

// Problem constants (fixed by setup_inputs)
#define B_   2
#define D_   64
#define KDIM 67          // D + 3 (points ++ xyz)
#define N1_  16384
#define N2_  16384

// Tiling
#define BM 128
#define BN 128
#define TM 8
#define TN 8
#define NTH 256

// Scratch: |f2_j|^2 per (b, j). Static device global (no allocation).
__device__ float g_sq2[B_ * N2_];

// ---------------------------------------------------------------------------
// Kernel A: precompute |f2_j|^2 = sum_d points2^2 + sum_d xyz2^2
// ---------------------------------------------------------------------------
__global__ void sq2_kernel(const float* __restrict__ xyz2,
                           const float* __restrict__ points2) {
    int idx = blockIdx.x * blockDim.x + threadIdx.x;
    if (idx >= B_ * N2_) return;
    int b = idx / N2_;
    int j = idx % N2_;
    const float* p = points2 + (size_t)b * D_ * N2_ + j;
    float s = 0.f;
    #pragma unroll
    for (int d = 0; d < D_; d++) { float v = p[(size_t)d * N2_]; s += v * v; }
    const float* x = xyz2 + (size_t)b * 3 * N2_ + j;
    #pragma unroll
    for (int d = 0; d < 3; d++) { float v = x[(size_t)d * N2_]; s += v * v; }
    g_sq2[idx] = s;
}

// ---------------------------------------------------------------------------
// Kernel B: fused GEMM + streaming argmin + output epilogue.
// __launch_bounds__(256, 2): cap regs at 128 so TWO blocks co-reside per SM.
// 256 blocks then fit in a single wave (capacity 296) AND occupancy doubles.
// ---------------------------------------------------------------------------
__global__ void __launch_bounds__(NTH, 2)
nn_kernel(const float* __restrict__ xyz1,
          const float* __restrict__ xyz2,
          const float* __restrict__ points1,
          const float* __restrict__ points2,
          float* __restrict__ out) {
    extern __shared__ float smem[];
    float* shA = smem;                   // [KDIM][BM]
    float* shB = smem + KDIM * BM;       // [KDIM][BN]
    float* shS = smem + 2 * KDIM * BM;   // [BN] : |f2|^2 for current tile

    const int b   = blockIdx.y;
    const int m0  = blockIdx.x * BM;
    const int tid = threadIdx.x;
    const int tx  = tid & 15;            // 0..15 -> n sub-tile
    const int ty  = tid >> 4;            // 0..15 -> m sub-tile

    const float* p1 = points1 + (size_t)b * D_ * N1_;
    const float* x1 = xyz1    + (size_t)b * 3  * N1_;
    const float* p2 = points2 + (size_t)b * D_ * N2_;
    const float* x2 = xyz2    + (size_t)b * 3  * N2_;

    // Load A tile [KDIM][BM] once (coalesced: contiguous 128-float rows)
    for (int idx = tid; idx < KDIM * BM; idx += NTH) {
        int k = idx >> 7;                // idx / 128
        int n = idx & 127;
        const float* src = (k < D_) ? (p1 + (size_t)k * N1_)
                                    : (x1 + (size_t)(k - D_) * N1_);
        shA[k * BM + n] = src[m0 + n];
    }

    float bestVal[TM];
    int   bestIdx[TM];
    #pragma unroll
    for (int i = 0; i < TM; i++) { bestVal[i] = FLT_MAX; bestIdx[i] = 0; }

    for (int n0 = 0; n0 < N2_; n0 += BN) {
        __syncthreads();   // protect shB/shS from previous iteration's readers
        for (int idx = tid; idx < KDIM * BN; idx += NTH) {
            int k = idx >> 7;
            int n = idx & 127;
            const float* src = (k < D_) ? (p2 + (size_t)k * N2_)
                                        : (x2 + (size_t)(k - D_) * N2_);
            shB[k * BN + n] = src[n0 + n];
        }
        if (tid < BN) shS[tid] = g_sq2[b * N2_ + n0 + tid];
        __syncthreads();

        float acc[TM][TN];
        #pragma unroll
        for (int i = 0; i < TM; i++)
            #pragma unroll
            for (int j = 0; j < TN; j++) acc[i][j] = 0.f;

        #pragma unroll 4
        for (int k = 0; k < KDIM; k++) {
            float4 a0 = *(const float4*)&shA[k * BM + ty * TM];
            float4 a1 = *(const float4*)&shA[k * BM + ty * TM + 4];
            float4 b0 = *(const float4*)&shB[k * BN + tx * TN];
            float4 b1 = *(const float4*)&shB[k * BN + tx * TN + 4];
            float av[TM] = {a0.x, a0.y, a0.z, a0.w, a1.x, a1.y, a1.z, a1.w};
            float bv[TN] = {b0.x, b0.y, b0.z, b0.w, b1.x, b1.y, b1.z, b1.w};
            #pragma unroll
            for (int i = 0; i < TM; i++)
                #pragma unroll
                for (int j = 0; j < TN; j++)
                    acc[i][j] += av[i] * bv[j];
        }

        // score = |f2_j|^2 - 2*dot ; running per-row argmin.
        // Indices are visited in strictly ascending order within a thread,
        // so strict '<' implements first-min tie-breaking with no extra cmp.
        #pragma unroll
        for (int j = 0; j < TN; j++) {
            int   jj = tx * TN + j;
            float s2 = shS[jj];
            int   gj = n0 + jj;
            #pragma unroll
            for (int i = 0; i < TM; i++) {
                float sc = fmaf(-2.f, acc[i][j], s2);
                if (sc < bestVal[i]) { bestVal[i] = sc; bestIdx[i] = gj; }
            }
        }
    }

    // Cross-thread argmin reduction: 16 candidates per row
    __syncthreads();
    float* sv = smem;                     // [BM][16] values
    int*   si = (int*)(smem + BM * 16);   // [BM][16] indices
    #pragma unroll
    for (int i = 0; i < TM; i++) {
        int row = ty * TM + i;
        sv[row * 16 + tx] = bestVal[i];
        si[row * 16 + tx] = bestIdx[i];
    }
    __syncthreads();

    if (tid < BM) {
        float bv = FLT_MAX;
        int   bi = 0x7FFFFFFF;
        #pragma unroll
        for (int t = 0; t < 16; t++) {
            float v  = sv[tid * 16 + t];
            int   ix = si[tid * 16 + t];
            if (v < bv || (v == bv && ix < bi)) { bv = v; bi = ix; }
        }
        int gi = m0 + tid;
        // Output layout (flattened, fp32): corres1 | corres2 | direction_xyz
        out[b * N1_ + gi]        = (float)gi;
        out[(B_ + b) * N1_ + gi] = (float)bi;
        float* dir = out + 2 * B_ * N1_;
        #pragma unroll
        for (int d = 0; d < 3; d++)
            dir[((size_t)b * 3 + d) * N1_ + gi] =
                x2[(size_t)d * N2_ + bi] - x1[(size_t)d * N1_ + gi];
    }
}

// ---------------------------------------------------------------------------
extern "C" void kernel_launch(void* const* d_in, const int* in_sizes, int n_in,
                              void* d_out, int out_size) {
    const float* xyz1    = (const float*)d_in[0];
    const float* xyz2    = (const float*)d_in[1];
    const float* points1 = (const float*)d_in[2];
    const float* points2 = (const float*)d_in[3];
    float* out = (float*)d_out;

    sq2_kernel<<<(B_ * N2_ + 255) / 256, 256>>>(xyz2, points2);

    int smem_bytes = (2 * KDIM * BM + BN) * sizeof(float);   // ~69 KB
    cudaFuncSetAttribute(nn_kernel,
                         cudaFuncAttributeMaxDynamicSharedMemorySize,
                         smem_bytes);
    dim3 grid(N1_ / BM, B_);
    nn_kernel<<<grid, NTH, smem_bytes>>>(xyz1, xyz2, points1, points2, out);
}